// round 2
// baseline (speedup 1.0000x reference)
#include <cuda_runtime.h>
#include <cuda_fp16.h>
#include <stdint.h>

static constexpr int SEQ = 2048;
static constexpr int VOC = 50257;
static constexpr int EMB = 768;

// Scratch (no allocation allowed -> __device__ globals)
__device__ __half g_Q[SEQ * EMB];
__device__ __half g_Km[SEQ * EMB];
__device__ __half g_V[SEQ * EMB];
__device__ float  g_scores[(size_t)SEQ * SEQ];
__device__ __half g_attn[(size_t)SEQ * SEQ];
__device__ __half g_ctx[SEQ * EMB];

__device__ __forceinline__ float toF(float v) { return v; }
__device__ __forceinline__ float toF(__half v) { return __half2float(v); }

#define BM 128
#define BN 64
#define BK 32
#define A_STRIDE (BK + 8)   // 40 halfs: conflict-free A fragment loads
#define B_STRIDE (BK + 2)   // 34 halfs: conflict-free B stores, ~2-way frag loads

// C[M,N] = (A[M,K] @ B) ; B is [K,N] row-major if !BT, [N,K] row-major if BT.
// Epilogue: v = (acc + bias[n]) * alpha; written fp16 or fp32.
template <typename TA, typename TB, bool BT, bool OUT_HALF, bool HAS_BIAS>
__global__ __launch_bounds__(256) void gemm_kernel(
    const TA* __restrict__ A, const TB* __restrict__ B,
    const float* __restrict__ bias,
    float* __restrict__ Cf, __half* __restrict__ Ch,
    int M, int N, int K, int lda, int ldb, int ldc, float alpha)
{
    __shared__ __align__(16) __half As[BM][A_STRIDE];
    __shared__ __align__(16) __half Bs[BN][B_STRIDE];   // Bs[n][k]

    const int tid  = threadIdx.x;
    const int row0 = blockIdx.y * BM;
    const int col0 = blockIdx.x * BN;

    const int warp = tid >> 5, lane = tid & 31;
    const int wm = (warp >> 1) * 32;   // 4 warps along M
    const int wn = (warp & 1) * 32;    // 2 warps along N
    const int g  = lane >> 2;          // groupID
    const int t4 = lane & 3;           // thread-in-group

    float acc[2][4][4];
#pragma unroll
    for (int mi = 0; mi < 2; mi++)
#pragma unroll
        for (int ni = 0; ni < 4; ni++)
#pragma unroll
            for (int c = 0; c < 4; c++) acc[mi][ni][c] = 0.f;

    // staging registers for next tile (overlap gmem latency with mma)
    float ra[16];
    float rb[8];

    const int ac = tid & 31;   // A: k within tile
    const int ar = tid >> 5;   // A: m base (stride 8)

    const int nTiles = (K + BK - 1) / BK;

    auto loadA = [&](int k0) {
#pragma unroll
        for (int i = 0; i < 16; i++) {
            int gk = k0 + ac;
            ra[i] = (gk < K) ? toF(A[(size_t)(row0 + ar + i * 8) * lda + gk]) : 0.f;
        }
    };
    auto loadB = [&](int k0) {
        if constexpr (BT) {
            const int kk = tid & 31, n0 = tid >> 5;
#pragma unroll
            for (int i = 0; i < 8; i++) {
                int gn = col0 + n0 + i * 8, gk = k0 + kk;
                rb[i] = (gn < N && gk < K) ? toF(B[(size_t)gn * ldb + gk]) : 0.f;
            }
        } else {
            const int n = tid & 63, kr = tid >> 6;
#pragma unroll
            for (int i = 0; i < 8; i++) {
                int gn = col0 + n, gk = k0 + kr + i * 4;
                rb[i] = (gn < N && gk < K) ? toF(B[(size_t)gk * ldb + gn]) : 0.f;
            }
        }
    };
    auto storeTiles = [&]() {
#pragma unroll
        for (int i = 0; i < 16; i++) As[ar + i * 8][ac] = __float2half(ra[i]);
        if constexpr (BT) {
            const int kk = tid & 31, n0 = tid >> 5;
#pragma unroll
            for (int i = 0; i < 8; i++) Bs[n0 + i * 8][kk] = __float2half(rb[i]);
        } else {
            const int n = tid & 63, kr = tid >> 6;
#pragma unroll
            for (int i = 0; i < 8; i++) Bs[n][kr + i * 4] = __float2half(rb[i]);
        }
    };

    loadA(0);
    loadB(0);

    for (int tIdx = 0; tIdx < nTiles; tIdx++) {
        storeTiles();
        __syncthreads();
        if (tIdx + 1 < nTiles) {   // prefetch next tile into registers
            loadA((tIdx + 1) * BK);
            loadB((tIdx + 1) * BK);
        }
#pragma unroll
        for (int ks = 0; ks < BK; ks += 16) {
            uint32_t a[2][4];
#pragma unroll
            for (int mi = 0; mi < 2; mi++) {
                const __half* ap = &As[wm + mi * 16 + g][ks + t4 * 2];
                a[mi][0] = *(const uint32_t*)ap;
                a[mi][1] = *(const uint32_t*)(ap + 8 * A_STRIDE);
                a[mi][2] = *(const uint32_t*)(ap + 8);
                a[mi][3] = *(const uint32_t*)(ap + 8 * A_STRIDE + 8);
            }
#pragma unroll
            for (int ni = 0; ni < 4; ni++) {
                const __half* bp = &Bs[wn + ni * 8 + g][ks + t4 * 2];
                uint32_t b0 = *(const uint32_t*)bp;
                uint32_t b1 = *(const uint32_t*)(bp + 8);
#pragma unroll
                for (int mi = 0; mi < 2; mi++) {
                    float* c = acc[mi][ni];
                    asm volatile(
                        "mma.sync.aligned.m16n8k16.row.col.f32.f16.f16.f32 "
                        "{%0,%1,%2,%3}, {%4,%5,%6,%7}, {%8,%9}, {%0,%1,%2,%3};\n"
                        : "+f"(c[0]), "+f"(c[1]), "+f"(c[2]), "+f"(c[3])
                        : "r"(a[mi][0]), "r"(a[mi][1]), "r"(a[mi][2]), "r"(a[mi][3]),
                          "r"(b0), "r"(b1));
                }
            }
        }
        __syncthreads();
    }

    // Epilogue
#pragma unroll
    for (int mi = 0; mi < 2; mi++) {
#pragma unroll
        for (int ni = 0; ni < 4; ni++) {
            int r = row0 + wm + mi * 16 + g;
            int cn = col0 + wn + ni * 8 + t4 * 2;
#pragma unroll
            for (int q = 0; q < 4; q++) {
                int rr = r + (q >> 1) * 8;
                int cc = cn + (q & 1);
                if (cc < N) {
                    float bv = 0.f;
                    if constexpr (HAS_BIAS) bv = bias[cc];
                    float v = (acc[mi][ni][q] + bv) * alpha;
                    if constexpr (OUT_HALF)
                        Ch[(size_t)rr * ldc + cc] = __float2half(v);
                    else
                        Cf[(size_t)rr * ldc + cc] = v;
                }
            }
        }
    }
}

__global__ __launch_bounds__(256) void softmax_kernel(
    const float* __restrict__ S_, __half* __restrict__ A_)
{
    __shared__ float red[8];
    const int row = blockIdx.x;
    const float* s = S_ + (size_t)row * SEQ;
    __half* a = A_ + (size_t)row * SEQ;
    const int tid = threadIdx.x;

    float v[8];
    float mx = -1e30f;
#pragma unroll
    for (int j = 0; j < 8; j++) {
        v[j] = s[tid + j * 256];
        mx = fmaxf(mx, v[j]);
    }
#pragma unroll
    for (int o = 16; o; o >>= 1) mx = fmaxf(mx, __shfl_xor_sync(0xffffffffu, mx, o));
    if ((tid & 31) == 0) red[tid >> 5] = mx;
    __syncthreads();
    mx = red[0];
#pragma unroll
    for (int i = 1; i < 8; i++) mx = fmaxf(mx, red[i]);

    float sum = 0.f;
#pragma unroll
    for (int j = 0; j < 8; j++) {
        v[j] = expf(v[j] - mx);
        sum += v[j];
    }
#pragma unroll
    for (int o = 16; o; o >>= 1) sum += __shfl_xor_sync(0xffffffffu, sum, o);
    __syncthreads();
    if ((tid & 31) == 0) red[tid >> 5] = sum;
    __syncthreads();
    float tot = 0.f;
#pragma unroll
    for (int i = 0; i < 8; i++) tot += red[i];
    float inv = 1.0f / tot;
#pragma unroll
    for (int j = 0; j < 8; j++) a[tid + j * 256] = __float2half(v[j] * inv);
}

extern "C" void kernel_launch(void* const* d_in, const int* in_sizes, int n_in,
                              void* d_out, int out_size)
{
    const float* x  = (const float*)d_in[0];
    const float* Wq = (const float*)d_in[1];
    const float* bq = (const float*)d_in[2];
    const float* Wk = (const float*)d_in[3];
    const float* bk = (const float*)d_in[4];
    const float* Wv = (const float*)d_in[5];
    const float* bv = (const float*)d_in[6];
    const float* Wo = (const float*)d_in[7];
    const float* bo = (const float*)d_in[8];
    float* out = (float*)d_out;

    __half *pQ, *pK, *pV, *pAttn, *pCtx;
    float* pS;
    cudaGetSymbolAddress((void**)&pQ, g_Q);
    cudaGetSymbolAddress((void**)&pK, g_Km);
    cudaGetSymbolAddress((void**)&pV, g_V);
    cudaGetSymbolAddress((void**)&pS, g_scores);
    cudaGetSymbolAddress((void**)&pAttn, g_attn);
    cudaGetSymbolAddress((void**)&pCtx, g_ctx);

    const float scale = 0.03608439182435161f;  // 1/sqrt(768), folded into Q store

    dim3 blk(256);
    dim3 gQKV(EMB / BN, SEQ / BM);             // 12 x 16
    dim3 gScore(SEQ / BN, SEQ / BM);           // 32 x 16
    dim3 gOut((VOC + BN - 1) / BN, SEQ / BM);  // 786 x 16

    // Q/K/V projections: read x + W in fp32, convert to fp16 in-kernel
    gemm_kernel<float, float, false, true, true><<<gQKV, blk>>>(
        x, Wq, bq, nullptr, pQ, SEQ, EMB, VOC, VOC, EMB, EMB, scale);
    gemm_kernel<float, float, false, true, true><<<gQKV, blk>>>(
        x, Wk, bk, nullptr, pK, SEQ, EMB, VOC, VOC, EMB, EMB, 1.0f);
    gemm_kernel<float, float, false, true, true><<<gQKV, blk>>>(
        x, Wv, bv, nullptr, pV, SEQ, EMB, VOC, VOC, EMB, EMB, 1.0f);

    // scores = (Q*scale) @ K^T   (B transposed: K stored [S, E] row-major)
    gemm_kernel<__half, __half, true, false, false><<<gScore, blk>>>(
        pQ, pK, nullptr, pS, nullptr, SEQ, SEQ, EMB, EMB, EMB, SEQ, 1.0f);

    softmax_kernel<<<SEQ, blk>>>(pS, pAttn);

    // ctx = attn @ V
    gemm_kernel<__half, __half, false, true, false><<<gQKV, blk>>>(
        pAttn, pV, nullptr, nullptr, pCtx, SEQ, EMB, SEQ, SEQ, EMB, EMB, 1.0f);

    // out = ctx @ Wo + bo
    gemm_kernel<__half, float, false, false, true><<<gOut, blk>>>(
        pCtx, Wo, bo, out, nullptr, SEQ, VOC, EMB, EMB, VOC, VOC, 1.0f);
}

// round 4
// speedup vs baseline: 5.7217x; 5.7217x over previous
#include <cuda_runtime.h>
#include <cuda_fp16.h>
#include <stdint.h>

static constexpr int SEQ = 2048;
static constexpr int VOC = 50257;
static constexpr int EMB = 768;
static constexpr int KPAD = 50272;   // VOC padded to multiple of 32 (K-dim of QKV gemm)
static constexpr int NPAD = 50304;   // VOC padded to multiple of 128 (N-dim of out gemm)

#define BM 128
#define BN 128
#define BK 32
#define STAGES 3
#define THREADS 256
#define A_HALF_PER_STAGE (BM * 40)   // 128 rows * (32+8) halves
#define B_HALF_PER_STAGE (BM * 40)   // max(128*40 [BT], 32*136 [non-BT]) = 5120
#define SMEM_BYTES (STAGES * (A_HALF_PER_STAGE + B_HALF_PER_STAGE) * 2)

// ---------------- scratch (__device__ globals; no allocation allowed) ---------
__device__ __half g_xh[(size_t)SEQ * KPAD];
__device__ __half g_Wqh[(size_t)KPAD * EMB];
__device__ __half g_Wkh[(size_t)KPAD * EMB];
__device__ __half g_Wvh[(size_t)KPAD * EMB];
__device__ __half g_Woh[(size_t)EMB * NPAD];
__device__ __half g_Q[SEQ * EMB];
__device__ __half g_Km[SEQ * EMB];
__device__ __half g_V[SEQ * EMB];
__device__ float  g_scores[(size_t)SEQ * SEQ];
__device__ __half g_attn[(size_t)SEQ * SEQ];
__device__ __half g_ctx[SEQ * EMB];

// ---------------- helpers ----------------------------------------------------
__device__ __forceinline__ void cp_async16(uint32_t dst, const void* src) {
    asm volatile("cp.async.cg.shared.global [%0], [%1], 16;\n" :: "r"(dst), "l"(src));
}
__device__ __forceinline__ void cp_commit() {
    asm volatile("cp.async.commit_group;\n");
}
__device__ __forceinline__ void cp_wait() {
    asm volatile("cp.async.wait_group %0;\n" :: "n"(STAGES - 2));
}
__device__ __forceinline__ void ldsm_x4(uint32_t* r, uint32_t addr) {
    asm volatile("ldmatrix.sync.aligned.m8n8.x4.shared.b16 {%0,%1,%2,%3}, [%4];\n"
                 : "=r"(r[0]), "=r"(r[1]), "=r"(r[2]), "=r"(r[3]) : "r"(addr));
}
__device__ __forceinline__ void ldsm_x4_t(uint32_t* r, uint32_t addr) {
    asm volatile("ldmatrix.sync.aligned.m8n8.x4.trans.shared.b16 {%0,%1,%2,%3}, [%4];\n"
                 : "=r"(r[0]), "=r"(r[1]), "=r"(r[2]), "=r"(r[3]) : "r"(addr));
}
__device__ __forceinline__ void mma16816(float* c, const uint32_t* a, const uint32_t* b) {
    asm volatile(
        "mma.sync.aligned.m16n8k16.row.col.f32.f16.f16.f32 "
        "{%0,%1,%2,%3}, {%4,%5,%6,%7}, {%8,%9}, {%0,%1,%2,%3};\n"
        : "+f"(c[0]), "+f"(c[1]), "+f"(c[2]), "+f"(c[3])
        : "r"(a[0]), "r"(a[1]), "r"(a[2]), "r"(a[3]), "r"(b[0]), "r"(b[1]));
}

// ---------------- conversion kernels -----------------------------------------
// Row-padded convert: src [rows][srcW] f32 -> dst [rows][dstW] f16, pad = 0.
__global__ __launch_bounds__(256) void cvt_pad(const float* __restrict__ s,
                                               __half2* __restrict__ d,
                                               int srcW, int dstW2, long rows) {
    long i = (long)blockIdx.x * blockDim.x + threadIdx.x;
    const long total = rows * dstW2;
    const long stride = (long)gridDim.x * blockDim.x;
    for (; i < total; i += stride) {
        long row = i / dstW2;
        int cp = (int)(i - row * dstW2);
        int col = cp * 2;
        const float* sr = s + row * srcW;
        float v0 = (col < srcW) ? sr[col] : 0.f;
        float v1 = (col + 1 < srcW) ? sr[col + 1] : 0.f;
        d[i] = __floats2half2_rn(v0, v1);
    }
}
// Contiguous convert with zero tail: first nValid elements from src, rest 0.
__global__ __launch_bounds__(256) void cvt_tail(const float* __restrict__ s,
                                                __half2* __restrict__ d,
                                                long nValid, long nTotal2) {
    long i = (long)blockIdx.x * blockDim.x + threadIdx.x;
    const long stride = (long)gridDim.x * blockDim.x;
    for (; i < nTotal2; i += stride) {
        long e = i * 2;
        float v0 = (e < nValid) ? s[e] : 0.f;
        float v1 = (e + 1 < nValid) ? s[e + 1] : 0.f;
        d[i] = __floats2half2_rn(v0, v1);
    }
}

// ---------------- pipelined fp16 GEMM ----------------------------------------
// C[M,N] = A[M,K] @ B (+bias)*alpha.  B row-major [K,N] if !BT, [N,K] if BT.
// All tile loads are full 16B, always in-bounds (dims padded by caller).
// FUSED3: blockIdx.x selects one of 3 (B, bias, output) sets; N is per-matrix.
template <bool BT, bool OUT_HALF, bool HAS_BIAS, bool FUSED3>
__global__ __launch_bounds__(THREADS, 2) void gemm2(
    const __half* __restrict__ A,
    const __half* __restrict__ B0, const __half* __restrict__ B1, const __half* __restrict__ B2,
    const float* __restrict__ bias0, const float* __restrict__ bias1, const float* __restrict__ bias2,
    float* __restrict__ Cf,
    __half* __restrict__ Ch0, __half* __restrict__ Ch1, __half* __restrict__ Ch2,
    int M, int N, int K, int lda, int ldb, int ldc, float alpha)
{
    extern __shared__ __half sm[];
    __half* As = sm;
    __half* Bs = sm + STAGES * A_HALF_PER_STAGE;

    const int tid = threadIdx.x;
    const int row0 = blockIdx.y * BM;

    const __half* B = B0;
    const float* bias = bias0;
    __half* Ch = Ch0;
    float aScale = alpha;
    int col0;
    if constexpr (FUSED3) {
        const int blocksPer = N / BN;
        const int sel = blockIdx.x / blocksPer;
        col0 = (blockIdx.x % blocksPer) * BN;
        if (sel == 1) { B = B1; bias = bias1; Ch = Ch1; aScale = 1.f; }
        else if (sel == 2) { B = B2; bias = bias2; Ch = Ch2; aScale = 1.f; }
    } else {
        col0 = blockIdx.x * BN;
    }

    const uint32_t smA = (uint32_t)__cvta_generic_to_shared(As);
    const uint32_t smB = (uint32_t)__cvta_generic_to_shared(Bs);

    const int nTiles = K / BK;   // K always a multiple of BK

    auto loadStage = [&](int t, int slot) {
        const int k0 = t * BK;
        // A tile: 128 rows x 32 halves -> 512 x 16B chunks
#pragma unroll
        for (int h = 0; h < 2; h++) {
            const int c = tid + h * 256;
            const int row = c >> 2, kc = (c & 3) * 8;
            const uint32_t dst = smA + (uint32_t)(slot * A_HALF_PER_STAGE + row * 40 + kc) * 2;
            cp_async16(dst, A + (size_t)(row0 + row) * lda + (k0 + kc));
        }
        if constexpr (BT) {
            // B tile [n][k]: 128 rows x 32 halves
#pragma unroll
            for (int h = 0; h < 2; h++) {
                const int c = tid + h * 256;
                const int nr = c >> 2, kc = (c & 3) * 8;
                const uint32_t dst = smB + (uint32_t)(slot * B_HALF_PER_STAGE + nr * 40 + kc) * 2;
                cp_async16(dst, B + (size_t)(col0 + nr) * ldb + (k0 + kc));
            }
        } else {
            // B tile [k][n]: 32 rows x 128 halves
#pragma unroll
            for (int h = 0; h < 2; h++) {
                const int c = tid + h * 256;
                const int kr = c >> 4, nc = (c & 15) * 8;
                const uint32_t dst = smB + (uint32_t)(slot * B_HALF_PER_STAGE + kr * 136 + nc) * 2;
                cp_async16(dst, B + (size_t)(k0 + kr) * ldb + (col0 + nc));
            }
        }
    };

    // warp tiling: 2 (M) x 4 (N) warps; warp tile 64x32
    const int warp = tid >> 5, lane = tid & 31;
    const int wm = (warp & 1) * 64;
    const int wn = (warp >> 1) * 32;
    const int g = lane >> 2, t4 = lane & 3;
    const int lrow = lane & 15;
    const int lcol8 = (lane >> 4) << 3;

    float acc[4][4][4];
#pragma unroll
    for (int mi = 0; mi < 4; mi++)
#pragma unroll
        for (int ni = 0; ni < 4; ni++)
#pragma unroll
            for (int q = 0; q < 4; q++) acc[mi][ni][q] = 0.f;

#pragma unroll
    for (int s = 0; s < STAGES - 1; s++) {
        loadStage(s, s);
        cp_commit();
    }

    for (int t = 0; t < nTiles; t++) {
        cp_wait();
        __syncthreads();

        const int nt = t + STAGES - 1;
        if (nt < nTiles) loadStage(nt, nt % STAGES);
        cp_commit();

        const int slot = t % STAGES;
        const uint32_t aBase = smA + (uint32_t)(slot * A_HALF_PER_STAGE) * 2;
        const uint32_t bBase = smB + (uint32_t)(slot * B_HALF_PER_STAGE) * 2;
        const __half* bPtrBase = Bs + slot * B_HALF_PER_STAGE;

#pragma unroll
        for (int ks = 0; ks < BK; ks += 16) {
            uint32_t a[4][4];
#pragma unroll
            for (int mi = 0; mi < 4; mi++) {
                const uint32_t addr = aBase + (uint32_t)((wm + mi * 16 + lrow) * 40 + ks + lcol8) * 2;
                ldsm_x4(a[mi], addr);
            }
            uint32_t b[4][2];
            if constexpr (BT) {
#pragma unroll
                for (int ni = 0; ni < 4; ni++) {
                    const __half* bp = bPtrBase + (wn + ni * 8 + g) * 40 + ks + t4 * 2;
                    b[ni][0] = *(const uint32_t*)bp;
                    b[ni][1] = *(const uint32_t*)(bp + 8);
                }
            } else {
#pragma unroll
                for (int nj = 0; nj < 2; nj++) {
                    uint32_t r[4];
                    const uint32_t addr = bBase + (uint32_t)((ks + lrow) * 136 + wn + nj * 16 + lcol8) * 2;
                    ldsm_x4_t(r, addr);
                    b[nj * 2][0] = r[0]; b[nj * 2][1] = r[1];
                    b[nj * 2 + 1][0] = r[2]; b[nj * 2 + 1][1] = r[3];
                }
            }
#pragma unroll
            for (int mi = 0; mi < 4; mi++)
#pragma unroll
                for (int ni = 0; ni < 4; ni++)
                    mma16816(acc[mi][ni], a[mi], b[ni]);
        }
    }

    // epilogue
#pragma unroll
    for (int mi = 0; mi < 4; mi++) {
#pragma unroll
        for (int ni = 0; ni < 4; ni++) {
            const int r = row0 + wm + mi * 16 + g;
            const int cn = col0 + wn + ni * 8 + t4 * 2;
#pragma unroll
            for (int q = 0; q < 4; q++) {
                const int rr = r + (q >> 1) * 8;
                const int cc = cn + (q & 1);
                if (cc < N) {
                    float bv = 0.f;
                    if constexpr (HAS_BIAS) bv = bias[cc];
                    const float v = (acc[mi][ni][q] + bv) * aScale;
                    if constexpr (OUT_HALF)
                        Ch[(size_t)rr * ldc + cc] = __float2half(v);
                    else
                        Cf[(size_t)rr * ldc + cc] = v;
                }
            }
        }
    }
}

// ---------------- softmax ----------------------------------------------------
__global__ __launch_bounds__(256) void softmax_kernel(
    const float* __restrict__ S_, __half* __restrict__ A_)
{
    __shared__ float red[8];
    const int row = blockIdx.x;
    const float* s = S_ + (size_t)row * SEQ;
    __half* a = A_ + (size_t)row * SEQ;
    const int tid = threadIdx.x;

    float v[8];
    float mx = -1e30f;
#pragma unroll
    for (int j = 0; j < 8; j++) {
        v[j] = s[tid + j * 256];
        mx = fmaxf(mx, v[j]);
    }
#pragma unroll
    for (int o = 16; o; o >>= 1) mx = fmaxf(mx, __shfl_xor_sync(0xffffffffu, mx, o));
    if ((tid & 31) == 0) red[tid >> 5] = mx;
    __syncthreads();
    mx = red[0];
#pragma unroll
    for (int i = 1; i < 8; i++) mx = fmaxf(mx, red[i]);

    float sum = 0.f;
#pragma unroll
    for (int j = 0; j < 8; j++) {
        v[j] = expf(v[j] - mx);
        sum += v[j];
    }
#pragma unroll
    for (int o = 16; o; o >>= 1) sum += __shfl_xor_sync(0xffffffffu, sum, o);
    __syncthreads();
    if ((tid & 31) == 0) red[tid >> 5] = sum;
    __syncthreads();
    float tot = 0.f;
#pragma unroll
    for (int i = 0; i < 8; i++) tot += red[i];
    const float inv = 1.0f / tot;
#pragma unroll
    for (int j = 0; j < 8; j++) a[tid + j * 256] = __float2half(v[j] * inv);
}

// ---------------- launch ------------------------------------------------------
extern "C" void kernel_launch(void* const* d_in, const int* in_sizes, int n_in,
                              void* d_out, int out_size)
{
    const float* x  = (const float*)d_in[0];
    const float* Wq = (const float*)d_in[1];
    const float* bq = (const float*)d_in[2];
    const float* Wk = (const float*)d_in[3];
    const float* bk = (const float*)d_in[4];
    const float* Wv = (const float*)d_in[5];
    const float* bv = (const float*)d_in[6];
    const float* Wo = (const float*)d_in[7];
    const float* bo = (const float*)d_in[8];
    float* out = (float*)d_out;

    __half *pxh, *pWqh, *pWkh, *pWvh, *pWoh, *pQ, *pK, *pV, *pAttn, *pCtx;
    float* pS;
    cudaGetSymbolAddress((void**)&pxh, g_xh);
    cudaGetSymbolAddress((void**)&pWqh, g_Wqh);
    cudaGetSymbolAddress((void**)&pWkh, g_Wkh);
    cudaGetSymbolAddress((void**)&pWvh, g_Wvh);
    cudaGetSymbolAddress((void**)&pWoh, g_Woh);
    cudaGetSymbolAddress((void**)&pQ, g_Q);
    cudaGetSymbolAddress((void**)&pK, g_Km);
    cudaGetSymbolAddress((void**)&pV, g_V);
    cudaGetSymbolAddress((void**)&pS, g_scores);
    cudaGetSymbolAddress((void**)&pAttn, g_attn);
    cudaGetSymbolAddress((void**)&pCtx, g_ctx);

    cudaFuncSetAttribute(gemm2<false, true, true, true>,
                         cudaFuncAttributeMaxDynamicSharedMemorySize, SMEM_BYTES);
    cudaFuncSetAttribute(gemm2<true, false, false, false>,
                         cudaFuncAttributeMaxDynamicSharedMemorySize, SMEM_BYTES);
    cudaFuncSetAttribute(gemm2<false, true, false, false>,
                         cudaFuncAttributeMaxDynamicSharedMemorySize, SMEM_BYTES);
    cudaFuncSetAttribute(gemm2<false, false, true, false>,
                         cudaFuncAttributeMaxDynamicSharedMemorySize, SMEM_BYTES);

    const float scale = 0.03608439182435161f;  // 1/sqrt(768)

    // fp32 -> fp16 with padding:
    // x [2048][50257] -> [2048][50272]
    cvt_pad<<<8192, 256>>>(x, (__half2*)pxh, VOC, KPAD / 2, SEQ);
    // Wq/Wk/Wv [50257][768] -> [50272][768] (zero pad rows)
    {
        const long nValid = (long)VOC * EMB;
        const long nTot2 = ((long)KPAD * EMB) / 2;
        cvt_tail<<<8192, 256>>>(Wq, (__half2*)pWqh, nValid, nTot2);
        cvt_tail<<<8192, 256>>>(Wk, (__half2*)pWkh, nValid, nTot2);
        cvt_tail<<<8192, 256>>>(Wv, (__half2*)pWvh, nValid, nTot2);
    }
    // Wo [768][50257] -> [768][50304]
    cvt_pad<<<8192, 256>>>(Wo, (__half2*)pWoh, VOC, NPAD / 2, EMB);

    dim3 blk(THREADS);

    // fused QKV projections (K = KPAD; pad contributes zeros).
    // Q gets 1/sqrt(d) folded in (incl. bias; linear, OK).
    gemm2<false, true, true, true><<<dim3(18, 16), blk, SMEM_BYTES>>>(
        pxh, pWqh, pWkh, pWvh, bq, bk, bv,
        nullptr, pQ, pK, pV,
        SEQ, EMB, KPAD, KPAD, EMB, EMB, scale);

    // scores = Qs @ K^T
    gemm2<true, false, false, false><<<dim3(16, 16), blk, SMEM_BYTES>>>(
        pQ, pK, nullptr, nullptr, nullptr, nullptr, nullptr,
        pS, nullptr, nullptr, nullptr,
        SEQ, SEQ, EMB, EMB, EMB, SEQ, 1.0f);

    softmax_kernel<<<SEQ, blk>>>(pS, pAttn);

    // ctx = attn @ V
    gemm2<false, true, false, false><<<dim3(6, 16), blk, SMEM_BYTES>>>(
        pAttn, pV, nullptr, nullptr, nullptr, nullptr, nullptr,
        nullptr, pCtx, nullptr, nullptr,
        SEQ, EMB, SEQ, SEQ, EMB, EMB, 1.0f);

    // out = ctx @ Wo + bo  (B stride NPAD; B loads always in-bounds)
    gemm2<false, false, true, false><<<dim3(NPAD / BN, 16), blk, SMEM_BYTES>>>(
        pCtx, pWoh, nullptr, nullptr, bo, nullptr, nullptr,
        out, nullptr, nullptr, nullptr,
        SEQ, VOC, EMB, EMB, NPAD, VOC, 1.0f);
}

// round 6
// speedup vs baseline: 6.1052x; 1.0670x over previous
#include <cuda_runtime.h>
#include <cuda_fp16.h>
#include <stdint.h>

static constexpr int SEQ  = 2048;
static constexpr int VOC  = 50257;
static constexpr int EMB  = 768;
static constexpr int KPAD = 50304;   // VOC padded to multiple of 64 (K of QKV gemm)
static constexpr int NPAD = 50304;   // VOC padded to multiple of 128 (N of out gemm)

#define BM 128
#define BN 128
#define BK 64
#define STAGES 3
#define THREADS 256
#define A_STRIDE 72                       // 64+8 halfs -> 144B rows, ldsm conflict-free
#define BNT_STRIDE 136                    // non-BT B rows: 128+8 halfs
#define A_HALF_PER_STAGE (BM * A_STRIDE)  // 9216
#define B_HALF_PER_STAGE (BM * A_STRIDE)  // max(128*72 [BT], 64*136=8704 [non-BT])
#define SMEM_BYTES (STAGES * (A_HALF_PER_STAGE + B_HALF_PER_STAGE) * 2)  // 110592

// ---------------- scratch (__device__ globals; no allocation allowed) ---------
__device__ __half g_xh[(size_t)SEQ * KPAD];
__device__ __half g_Wqh[(size_t)KPAD * EMB];
__device__ __half g_Wkh[(size_t)KPAD * EMB];
__device__ __half g_Wvh[(size_t)KPAD * EMB];
__device__ __half g_Woh[(size_t)EMB * NPAD];
__device__ __half g_Q[SEQ * EMB];
__device__ __half g_Km[SEQ * EMB];
__device__ __half g_V[SEQ * EMB];
__device__ float  g_scores[(size_t)SEQ * SEQ];
__device__ __half g_attn[(size_t)SEQ * SEQ];
__device__ __half g_ctx[SEQ * EMB];

// ---------------- helpers ----------------------------------------------------
__device__ __forceinline__ void cp_async16(uint32_t dst, const void* src) {
    asm volatile("cp.async.cg.shared.global [%0], [%1], 16;\n" :: "r"(dst), "l"(src));
}
__device__ __forceinline__ void cp_commit() {
    asm volatile("cp.async.commit_group;\n");
}
__device__ __forceinline__ void cp_wait() {
    asm volatile("cp.async.wait_group %0;\n" :: "n"(STAGES - 2));
}
__device__ __forceinline__ void ldsm_x4(uint32_t* r, uint32_t addr) {
    asm volatile("ldmatrix.sync.aligned.m8n8.x4.shared.b16 {%0,%1,%2,%3}, [%4];\n"
                 : "=r"(r[0]), "=r"(r[1]), "=r"(r[2]), "=r"(r[3]) : "r"(addr));
}
__device__ __forceinline__ void ldsm_x4_t(uint32_t* r, uint32_t addr) {
    asm volatile("ldmatrix.sync.aligned.m8n8.x4.trans.shared.b16 {%0,%1,%2,%3}, [%4];\n"
                 : "=r"(r[0]), "=r"(r[1]), "=r"(r[2]), "=r"(r[3]) : "r"(addr));
}
__device__ __forceinline__ void mma16816(float* c, const uint32_t* a, const uint32_t* b) {
    asm volatile(
        "mma.sync.aligned.m16n8k16.row.col.f32.f16.f16.f32 "
        "{%0,%1,%2,%3}, {%4,%5,%6,%7}, {%8,%9}, {%0,%1,%2,%3};\n"
        : "+f"(c[0]), "+f"(c[1]), "+f"(c[2]), "+f"(c[3])
        : "r"(a[0]), "r"(a[1]), "r"(a[2]), "r"(a[3]), "r"(b[0]), "r"(b[1]));
}

// ---------------- conversion kernels -----------------------------------------
__global__ __launch_bounds__(256) void cvt_pad(const float* __restrict__ s,
                                               __half2* __restrict__ d,
                                               int srcW, int dstW2, long rows) {
    long i = (long)blockIdx.x * blockDim.x + threadIdx.x;
    const long total = rows * dstW2;
    const long stride = (long)gridDim.x * blockDim.x;
    for (; i < total; i += stride) {
        long row = i / dstW2;
        int col = (int)(i - row * dstW2) * 2;
        const float* sr = s + row * (size_t)srcW;
        float v0 = (col < srcW) ? sr[col] : 0.f;
        float v1 = (col + 1 < srcW) ? sr[col + 1] : 0.f;
        d[i] = __floats2half2_rn(v0, v1);
    }
}
__global__ __launch_bounds__(256) void cvt_tail(const float* __restrict__ s,
                                                __half2* __restrict__ d,
                                                long nValid, long nTotal2) {
    long i = (long)blockIdx.x * blockDim.x + threadIdx.x;
    const long stride = (long)gridDim.x * blockDim.x;
    for (; i < nTotal2; i += stride) {
        long e = i * 2;
        float v0 = (e < nValid) ? s[e] : 0.f;
        float v1 = (e + 1 < nValid) ? s[e + 1] : 0.f;
        d[i] = __floats2half2_rn(v0, v1);
    }
}

// ---------------- pipelined fp16 GEMM (BK=64, 3 stages) -----------------------
// C[M,N] = A[M,K] @ B (+bias)*alpha.  B row-major [K,N] if !BT, [N,K] if BT.
// All tile loads are full 16B, always in-bounds (dims padded by caller).
// FUSED3: blockIdx.x selects one of 3 (B, bias, output) sets; N is per-matrix.
template <bool BT, bool OUT_HALF, bool HAS_BIAS, bool FUSED3>
__global__ __launch_bounds__(THREADS, 2) void gemm2(
    const __half* __restrict__ A,
    const __half* __restrict__ B0, const __half* __restrict__ B1, const __half* __restrict__ B2,
    const float* __restrict__ bias0, const float* __restrict__ bias1, const float* __restrict__ bias2,
    float* __restrict__ Cf,
    __half* __restrict__ Ch0, __half* __restrict__ Ch1, __half* __restrict__ Ch2,
    int M, int N, int K, int lda, int ldb, int ldc, float alpha)
{
    extern __shared__ __half sm[];
    __half* As = sm;
    __half* Bs = sm + STAGES * A_HALF_PER_STAGE;

    const int tid = threadIdx.x;
    const int row0 = blockIdx.y * BM;

    const __half* B = B0;
    const float* bias = bias0;
    __half* Ch = Ch0;
    float aScale = alpha;
    int col0;
    if constexpr (FUSED3) {
        const int blocksPer = N / BN;
        const int sel = blockIdx.x / blocksPer;
        col0 = (blockIdx.x % blocksPer) * BN;
        if (sel == 1) { B = B1; bias = bias1; Ch = Ch1; aScale = 1.f; }
        else if (sel == 2) { B = B2; bias = bias2; Ch = Ch2; aScale = 1.f; }
    } else {
        col0 = blockIdx.x * BN;
    }

    const uint32_t smA = (uint32_t)__cvta_generic_to_shared(As);
    const uint32_t smB = (uint32_t)__cvta_generic_to_shared(Bs);

    const int nTiles = K / BK;   // K always a multiple of BK

    auto loadStage = [&](int t, int slot) {
        const int k0 = t * BK;
        // A tile: 128 rows x 64 halfs -> 1024 x 16B chunks, 4 per thread
#pragma unroll
        for (int h = 0; h < 4; h++) {
            const int c = tid + h * 256;
            const int row = c >> 3, kc = (c & 7) * 8;
            const uint32_t dst = smA + (uint32_t)(slot * A_HALF_PER_STAGE + row * A_STRIDE + kc) * 2;
            cp_async16(dst, A + (size_t)(row0 + row) * lda + (k0 + kc));
        }
        if constexpr (BT) {
            // B tile [n][k]: 128 rows x 64 halfs
#pragma unroll
            for (int h = 0; h < 4; h++) {
                const int c = tid + h * 256;
                const int nr = c >> 3, kc = (c & 7) * 8;
                const uint32_t dst = smB + (uint32_t)(slot * B_HALF_PER_STAGE + nr * A_STRIDE + kc) * 2;
                cp_async16(dst, B + (size_t)(col0 + nr) * ldb + (k0 + kc));
            }
        } else {
            // B tile [k][n]: 64 rows x 128 halfs
#pragma unroll
            for (int h = 0; h < 4; h++) {
                const int c = tid + h * 256;
                const int kr = c >> 4, nc = (c & 15) * 8;
                const uint32_t dst = smB + (uint32_t)(slot * B_HALF_PER_STAGE + kr * BNT_STRIDE + nc) * 2;
                cp_async16(dst, B + (size_t)(k0 + kr) * ldb + (col0 + nc));
            }
        }
    };

    // warp tiling: 2 (M) x 4 (N) warps; warp tile 64x32
    const int warp = tid >> 5, lane = tid & 31;
    const int wm = (warp & 1) * 64;
    const int wn = (warp >> 1) * 32;
    const int g = lane >> 2, t4 = lane & 3;
    const int lrow = lane & 15;
    const int lcol8 = (lane >> 4) << 3;

    float acc[4][4][4];
#pragma unroll
    for (int mi = 0; mi < 4; mi++)
#pragma unroll
        for (int ni = 0; ni < 4; ni++)
#pragma unroll
            for (int q = 0; q < 4; q++) acc[mi][ni][q] = 0.f;

#pragma unroll
    for (int s = 0; s < STAGES - 1; s++) {
        loadStage(s, s);
        cp_commit();
    }

    for (int t = 0; t < nTiles; t++) {
        cp_wait();
        __syncthreads();

        const int nt = t + STAGES - 1;
        if (nt < nTiles) loadStage(nt, nt % STAGES);
        cp_commit();

        const int slot = t % STAGES;
        const uint32_t aBase = smA + (uint32_t)(slot * A_HALF_PER_STAGE) * 2;
        const uint32_t bBase = smB + (uint32_t)(slot * B_HALF_PER_STAGE) * 2;
        const __half* bPtrBase = Bs + slot * B_HALF_PER_STAGE;

#pragma unroll
        for (int ks = 0; ks < BK; ks += 16) {
            uint32_t a[4][4];
#pragma unroll
            for (int mi = 0; mi < 4; mi++) {
                const uint32_t addr = aBase + (uint32_t)((wm + mi * 16 + lrow) * A_STRIDE + ks + lcol8) * 2;
                ldsm_x4(a[mi], addr);
            }
            uint32_t b[4][2];
            if constexpr (BT) {
#pragma unroll
                for (int ni = 0; ni < 4; ni++) {
                    const __half* bp = bPtrBase + (wn + ni * 8 + g) * A_STRIDE + ks + t4 * 2;
                    b[ni][0] = *(const uint32_t*)bp;
                    b[ni][1] = *(const uint32_t*)(bp + 8);
                }
            } else {
#pragma unroll
                for (int nj = 0; nj < 2; nj++) {
                    uint32_t r[4];
                    const uint32_t addr = bBase + (uint32_t)((ks + lrow) * BNT_STRIDE + wn + nj * 16 + lcol8) * 2;
                    ldsm_x4_t(r, addr);
                    b[nj * 2][0] = r[0]; b[nj * 2][1] = r[1];
                    b[nj * 2 + 1][0] = r[2]; b[nj * 2 + 1][1] = r[3];
                }
            }
#pragma unroll
            for (int mi = 0; mi < 4; mi++)
#pragma unroll
                for (int ni = 0; ni < 4; ni++)
                    mma16816(acc[mi][ni], a[mi], b[ni]);
        }
    }

    // epilogue
#pragma unroll
    for (int mi = 0; mi < 4; mi++) {
#pragma unroll
        for (int ni = 0; ni < 4; ni++) {
            const int r = row0 + wm + mi * 16 + g;
            const int cn = col0 + wn + ni * 8 + t4 * 2;
#pragma unroll
            for (int q = 0; q < 4; q++) {
                const int rr = r + (q >> 1) * 8;
                const int cc = cn + (q & 1);
                if (cc < N) {
                    float bv = 0.f;
                    if constexpr (HAS_BIAS) bv = bias[cc];
                    const float v = (acc[mi][ni][q] + bv) * aScale;
                    if constexpr (OUT_HALF)
                        Ch[(size_t)rr * ldc + cc] = __float2half(v);
                    else
                        Cf[(size_t)rr * ldc + cc] = v;
                }
            }
        }
    }
}

// ---------------- softmax ----------------------------------------------------
__global__ __launch_bounds__(256) void softmax_kernel(
    const float* __restrict__ S_, __half* __restrict__ A_)
{
    __shared__ float red[8];
    const int row = blockIdx.x;
    const float* s = S_ + (size_t)row * SEQ;
    __half* a = A_ + (size_t)row * SEQ;
    const int tid = threadIdx.x;

    float v[8];
    float mx = -1e30f;
#pragma unroll
    for (int j = 0; j < 8; j++) {
        v[j] = s[tid + j * 256];
        mx = fmaxf(mx, v[j]);
    }
#pragma unroll
    for (int o = 16; o; o >>= 1) mx = fmaxf(mx, __shfl_xor_sync(0xffffffffu, mx, o));
    if ((tid & 31) == 0) red[tid >> 5] = mx;
    __syncthreads();
    mx = red[0];
#pragma unroll
    for (int i = 1; i < 8; i++) mx = fmaxf(mx, red[i]);

    float sum = 0.f;
#pragma unroll
    for (int j = 0; j < 8; j++) {
        v[j] = expf(v[j] - mx);
        sum += v[j];
    }
#pragma unroll
    for (int o = 16; o; o >>= 1) sum += __shfl_xor_sync(0xffffffffu, sum, o);
    __syncthreads();
    if ((tid & 31) == 0) red[tid >> 5] = sum;
    __syncthreads();
    float tot = 0.f;
#pragma unroll
    for (int i = 0; i < 8; i++) tot += red[i];
    const float inv = 1.0f / tot;
#pragma unroll
    for (int j = 0; j < 8; j++) a[tid + j * 256] = __float2half(v[j] * inv);
}

// ---------------- launch ------------------------------------------------------
extern "C" void kernel_launch(void* const* d_in, const int* in_sizes, int n_in,
                              void* d_out, int out_size)
{
    const float* x  = (const float*)d_in[0];
    const float* Wq = (const float*)d_in[1];
    const float* bq = (const float*)d_in[2];
    const float* Wk = (const float*)d_in[3];
    const float* bk = (const float*)d_in[4];
    const float* Wv = (const float*)d_in[5];
    const float* bv = (const float*)d_in[6];
    const float* Wo = (const float*)d_in[7];
    const float* bo = (const float*)d_in[8];
    float* out = (float*)d_out;

    __half *pxh, *pWqh, *pWkh, *pWvh, *pWoh, *pQ, *pK, *pV, *pAttn, *pCtx;
    float* pS;
    cudaGetSymbolAddress((void**)&pxh, g_xh);
    cudaGetSymbolAddress((void**)&pWqh, g_Wqh);
    cudaGetSymbolAddress((void**)&pWkh, g_Wkh);
    cudaGetSymbolAddress((void**)&pWvh, g_Wvh);
    cudaGetSymbolAddress((void**)&pWoh, g_Woh);
    cudaGetSymbolAddress((void**)&pQ, g_Q);
    cudaGetSymbolAddress((void**)&pK, g_Km);
    cudaGetSymbolAddress((void**)&pV, g_V);
    cudaGetSymbolAddress((void**)&pS, g_scores);
    cudaGetSymbolAddress((void**)&pAttn, g_attn);
    cudaGetSymbolAddress((void**)&pCtx, g_ctx);

    cudaFuncSetAttribute(gemm2<false, true, true, true>,
                         cudaFuncAttributeMaxDynamicSharedMemorySize, SMEM_BYTES);
    cudaFuncSetAttribute(gemm2<true, false, false, false>,
                         cudaFuncAttributeMaxDynamicSharedMemorySize, SMEM_BYTES);
    cudaFuncSetAttribute(gemm2<false, true, false, false>,
                         cudaFuncAttributeMaxDynamicSharedMemorySize, SMEM_BYTES);
    cudaFuncSetAttribute(gemm2<false, false, true, false>,
                         cudaFuncAttributeMaxDynamicSharedMemorySize, SMEM_BYTES);

    const float scale = 0.03608439182435161f;  // 1/sqrt(768)

    // fp32 -> fp16 with padding:
    cvt_pad<<<8192, 256>>>(x, (__half2*)pxh, VOC, KPAD / 2, SEQ);
    {
        const long nValid = (long)VOC * EMB;
        const long nTot2 = ((long)KPAD * EMB) / 2;
        cvt_tail<<<8192, 256>>>(Wq, (__half2*)pWqh, nValid, nTot2);
        cvt_tail<<<8192, 256>>>(Wk, (__half2*)pWkh, nValid, nTot2);
        cvt_tail<<<8192, 256>>>(Wv, (__half2*)pWvh, nValid, nTot2);
    }
    cvt_pad<<<8192, 256>>>(Wo, (__half2*)pWoh, VOC, NPAD / 2, EMB);

    dim3 blk(THREADS);

    // fused QKV projections (K = KPAD; pad rows are zero).
    gemm2<false, true, true, true><<<dim3(18, 16), blk, SMEM_BYTES>>>(
        pxh, pWqh, pWkh, pWvh, bq, bk, bv,
        nullptr, pQ, pK, pV,
        SEQ, EMB, KPAD, KPAD, EMB, EMB, scale);

    // scores = Qs @ K^T
    gemm2<true, false, false, false><<<dim3(16, 16), blk, SMEM_BYTES>>>(
        pQ, pK, nullptr, nullptr, nullptr, nullptr, nullptr,
        pS, nullptr, nullptr, nullptr,
        SEQ, SEQ, EMB, EMB, EMB, SEQ, 1.0f);

    softmax_kernel<<<SEQ, blk>>>(pS, pAttn);

    // ctx = attn @ V
    gemm2<false, true, false, false><<<dim3(6, 16), blk, SMEM_BYTES>>>(
        pAttn, pV, nullptr, nullptr, nullptr, nullptr, nullptr,
        nullptr, pCtx, nullptr, nullptr,
        SEQ, EMB, SEQ, SEQ, EMB, EMB, 1.0f);

    // out = ctx @ Wo + bo  (B stride NPAD; B loads always in-bounds)
    gemm2<false, false, true, false><<<dim3(NPAD / BN, 16), blk, SMEM_BYTES>>>(
        pCtx, pWoh, nullptr, nullptr, bo, nullptr, nullptr,
        out, nullptr, nullptr, nullptr,
        SEQ, VOC, EMB, EMB, NPAD, VOC, 1.0f);
}